// round 12
// baseline (speedup 1.0000x reference)
#include <cuda_runtime.h>
#include <cuda_bf16.h>

// Problem constants
#define BATCH 8
#define SQ 2048
#define SK 2048
#define DIM 1024
#define H 8
#define ROWS (BATCH * SQ)   // 16384
#define KSPLIT 8
#define KS_LEN (SK / KSPLIT)  // 256

// Scratch (allocation-free: __device__ globals)
__device__ float g_q[ROWS * H];
__device__ float g_k[ROWS * H];
__device__ float g_v[ROWS * H];
__device__ float g_pn[KSPLIT * ROWS * H];  // partial numerators
__device__ float g_pd[KSPLIT * ROWS];      // partial denominators

typedef unsigned long long ull;

__device__ __forceinline__ ull ffma2(ull a, ull b, ull c) {
    ull d;
    asm("fma.rn.f32x2 %0, %1, %2, %3;" : "=l"(d) : "l"(a), "l"(b), "l"(c));
    return d;
}
__device__ __forceinline__ ull fmul2(ull a, ull b) {
    ull d;
    asm("mul.rn.f32x2 %0, %1, %2;" : "=l"(d) : "l"(a), "l"(b));
    return d;
}
__device__ __forceinline__ float f2_lo(ull a) { return __uint_as_float((unsigned)(a & 0xffffffffull)); }
__device__ __forceinline__ float f2_hi(ull a) { return __uint_as_float((unsigned)(a >> 32)); }
__device__ __forceinline__ ull f2_pack(float lo, float hi) {
    ull p;
    asm("mov.b64 %0, {%1, %2};" : "=l"(p) : "r"(__float_as_uint(lo)), "r"(__float_as_uint(hi)));
    return p;
}

// ---------------------------------------------------------------------------
// Kernel 1: fused q/k/v projection. grid = 3 * 256 blocks x 256 threads.
//   path = blockIdx.x >> 8 selects (X, W, bias, Y). 64 rows/block,
//   8 rows/warp as two batches of four (R=4 W-reuse -> 8 KB LDS/row).
//   d-loop: 8 chunks of 128 with DOUBLE-BUFFERED next-chunk prefetch:
//   chunk u+1's 4 LDG.128 are issued before chunk u's FMAs, so each warp
//   keeps 2 KB outstanding through the whole compute phase (R11 had zero
//   outstanding during FMA bursts -> DRAM stuck at 31%).
//   Regs: acc 64 + xv 2x16 + misc ~ 120 -> no spill at (256,2).
// ---------------------------------------------------------------------------
#define PROJ_WPITCH 1032   // 1024 + 8 pad floats
__global__ void __launch_bounds__(256, 2) proj_fused_kernel(
    const float* __restrict__ x, const float* __restrict__ ctx,
    const float* __restrict__ Wq, const float* __restrict__ bq,
    const float* __restrict__ Wk, const float* __restrict__ bk,
    const float* __restrict__ Wv, const float* __restrict__ bv,
    float* __restrict__ q, float* __restrict__ k, float* __restrict__ v)
{
    __shared__ float sw[H * PROJ_WPITCH];   // 33 KB

    const int tid = threadIdx.x;
    const int warp = tid >> 5;
    const int lane = tid & 31;

    const int path = blockIdx.x >> 8;       // 0 = q, 1 = k, 2 = v
    const int blk  = blockIdx.x & 255;

    const float* X    = (path == 0) ? x  : ctx;
    const float* W    = (path == 0) ? Wq : (path == 1) ? Wk : Wv;
    const float* bias = (path == 0) ? bq : (path == 1) ? bk : bv;
    float*       Y    = (path == 0) ? q  : (path == 1) ? k  : v;

    // Stage W transposed via float4 global loads:
    //   i in [0, 2048): d = i>>1, hg = (i&1)*4 -> W[d*8 + hg .. +4]
    for (int i = tid; i < DIM * 2; i += 256) {
        int d = i >> 1, hg = (i & 1) * 4;
        float4 w4 = *reinterpret_cast<const float4*>(W + d * H + hg);
        sw[(hg + 0) * PROJ_WPITCH + d] = w4.x;
        sw[(hg + 1) * PROJ_WPITCH + d] = w4.y;
        sw[(hg + 2) * PROJ_WPITCH + d] = w4.z;
        sw[(hg + 3) * PROJ_WPITCH + d] = w4.w;
    }
    float bias_lane = (lane < H) ? bias[lane] : 0.0f;
    __syncthreads();

    const int block_row0 = blk * 64;

#pragma unroll 1
    for (int b4 = 0; b4 < 2; ++b4) {
        const int row0 = block_row0 + warp * 8 + b4 * 4;
        const float* xr = X + (size_t)row0 * DIM + lane * 4;

        ull acc0[H], acc1[H], acc2[H], acc3[H];
#pragma unroll
        for (int h = 0; h < H; ++h) {
            acc0[h] = 0ull; acc1[h] = 0ull; acc2[h] = 0ull; acc3[h] = 0ull;
        }

        // Prologue: load chunk 0 for all 4 rows
        ulonglong2 cur0 = *reinterpret_cast<const ulonglong2*>(xr);
        ulonglong2 cur1 = *reinterpret_cast<const ulonglong2*>(xr + DIM);
        ulonglong2 cur2 = *reinterpret_cast<const ulonglong2*>(xr + 2 * DIM);
        ulonglong2 cur3 = *reinterpret_cast<const ulonglong2*>(xr + 3 * DIM);

        // Pipelined u-loop (fully unrolled): prefetch u+1, compute u
#pragma unroll
        for (int u = 0; u < 8; ++u) {
            ulonglong2 nxt0, nxt1, nxt2, nxt3;
            if (u < 7) {
                const float* xn = xr + (u + 1) * 128;
                nxt0 = *reinterpret_cast<const ulonglong2*>(xn);
                nxt1 = *reinterpret_cast<const ulonglong2*>(xn + DIM);
                nxt2 = *reinterpret_cast<const ulonglong2*>(xn + 2 * DIM);
                nxt3 = *reinterpret_cast<const ulonglong2*>(xn + 3 * DIM);
            }

            const int d = lane * 4 + u * 128;
#pragma unroll
            for (int h = 0; h < H; ++h) {
                ulonglong2 wv = *reinterpret_cast<const ulonglong2*>(&sw[h * PROJ_WPITCH + d]);
                acc0[h] = ffma2(cur0.x, wv.x, acc0[h]);
                acc0[h] = ffma2(cur0.y, wv.y, acc0[h]);
                acc1[h] = ffma2(cur1.x, wv.x, acc1[h]);
                acc1[h] = ffma2(cur1.y, wv.y, acc1[h]);
                acc2[h] = ffma2(cur2.x, wv.x, acc2[h]);
                acc2[h] = ffma2(cur2.y, wv.y, acc2[h]);
                acc3[h] = ffma2(cur3.x, wv.x, acc3[h]);
                acc3[h] = ffma2(cur3.y, wv.y, acc3[h]);
            }

            if (u < 7) { cur0 = nxt0; cur1 = nxt1; cur2 = nxt2; cur3 = nxt3; }
        }

        // Reduce across lanes; lane h keeps head h's sum
#pragma unroll
        for (int r = 0; r < 4; ++r) {
            float keep = 0.0f;
#pragma unroll
            for (int h = 0; h < H; ++h) {
                ull a = (r == 0) ? acc0[h] : (r == 1) ? acc1[h] : (r == 2) ? acc2[h] : acc3[h];
                float s = f2_lo(a) + f2_hi(a);
                s += __shfl_xor_sync(0xffffffffu, s, 16);
                s += __shfl_xor_sync(0xffffffffu, s, 8);
                s += __shfl_xor_sync(0xffffffffu, s, 4);
                s += __shfl_xor_sync(0xffffffffu, s, 2);
                s += __shfl_xor_sync(0xffffffffu, s, 1);
                if (lane == h) keep = s;
            }
            if (lane < H) Y[(size_t)(row0 + r) * H + lane] = keep + bias_lane;
        }
    }
}

// ---------------------------------------------------------------------------
// Kernel 2: attention partials with key-split.
//   grid = 8 batches x 16 qchunks x 8 ksplits = 1024 blocks x 128 threads.
//   One thread per query; each block covers 256 keys (tile in smem, 16 KB).
//   Softmax without max-subtraction -> split partials add exactly.
// ---------------------------------------------------------------------------
__global__ void __launch_bounds__(128) attn_part_kernel(
    const float* __restrict__ q, const float* __restrict__ k,
    const float* __restrict__ v, float* __restrict__ pn,
    float* __restrict__ pd)
{
    __shared__ float ks[KS_LEN * H];   // 8 KB
    __shared__ float vs[KS_LEN * H];   // 8 KB

    const int tid = threadIdx.x;
    const int bb = blockIdx.x >> 7;            // batch
    const int qc = (blockIdx.x >> 3) & 15;     // query chunk
    const int sp = blockIdx.x & 7;             // key split
    const int row = bb * SQ + qc * 128 + tid;
    const int kbase = bb * SK + sp * KS_LEN;

    // Cooperative tile load: 256 keys x 8 floats for k and v
    {
        const float4* kg = reinterpret_cast<const float4*>(k + (size_t)kbase * H);
        const float4* vg = reinterpret_cast<const float4*>(v + (size_t)kbase * H);
        float4* ks4 = reinterpret_cast<float4*>(ks);
        float4* vs4 = reinterpret_cast<float4*>(vs);
#pragma unroll
        for (int i = 0; i < (KS_LEN * H / 4) / 128; ++i) {
            ks4[tid + i * 128] = kg[tid + i * 128];
            vs4[tid + i * 128] = vg[tid + i * 128];
        }
    }

    // Query in registers as four f32x2 packs
    ulonglong2 qa = *reinterpret_cast<const ulonglong2*>(q + (size_t)row * H);
    ulonglong2 qb = *reinterpret_cast<const ulonglong2*>(q + (size_t)row * H + 4);
    const ull q01 = qa.x, q23 = qa.y, q45 = qb.x, q67 = qb.y;

    __syncthreads();

    ull acc0 = 0ull, acc1 = 0ull, acc2 = 0ull, acc3 = 0ull;
    float denom = 0.0f;

#pragma unroll 8
    for (int t = 0; t < KS_LEN; ++t) {
        ulonglong2 k0 = *reinterpret_cast<const ulonglong2*>(&ks[t * H]);
        ulonglong2 k1 = *reinterpret_cast<const ulonglong2*>(&ks[t * H + 4]);
        ull s2 = fmul2(q67, k1.y);
        s2 = ffma2(q45, k1.x, s2);
        s2 = ffma2(q23, k0.y, s2);
        s2 = ffma2(q01, k0.x, s2);
        float s = f2_lo(s2) + f2_hi(s2);
        float e = __expf(s);
        denom += e;
        ull e2 = f2_pack(e, e);
        ulonglong2 v0 = *reinterpret_cast<const ulonglong2*>(&vs[t * H]);
        ulonglong2 v1 = *reinterpret_cast<const ulonglong2*>(&vs[t * H + 4]);
        acc0 = ffma2(e2, v0.x, acc0);
        acc1 = ffma2(e2, v0.y, acc1);
        acc2 = ffma2(e2, v1.x, acc2);
        acc3 = ffma2(e2, v1.y, acc3);
    }

    float4 o0, o1;
    o0.x = f2_lo(acc0); o0.y = f2_hi(acc0);
    o0.z = f2_lo(acc1); o0.w = f2_hi(acc1);
    o1.x = f2_lo(acc2); o1.y = f2_hi(acc2);
    o1.z = f2_lo(acc3); o1.w = f2_hi(acc3);
    float* pnr = pn + ((size_t)sp * ROWS + row) * H;
    *reinterpret_cast<float4*>(pnr)     = o0;
    *reinterpret_cast<float4*>(pnr + 4) = o1;
    pd[(size_t)sp * ROWS + row] = denom;
}

// ---------------------------------------------------------------------------
// Kernel 3: combine split-K partials + output projection.
//   grid = 1024 blocks x 256 threads, 16 rows/block.
//   Fold parallelized: threads 0..127 each fetch one (row, split) partial
//   into smem; threads 0..15 then fold 8 splits from smem (LDS, not LDG).
//   All threads project with Wo slice in registers (8 x float4 per thread).
// ---------------------------------------------------------------------------
#define OUT_RPB 16
__global__ void __launch_bounds__(256) outproj_kernel(
    const float* __restrict__ pn, const float* __restrict__ pd,
    const float* __restrict__ Wo, const float* __restrict__ bo,
    float* __restrict__ out)
{
    __shared__ float ps[OUT_RPB][KSPLIT][12];  // 9 used, pad to 12
    __shared__ float a_sm[OUT_RPB][H];

    const int t = threadIdx.x;
    const int j = t * 4;
    const int row0 = blockIdx.x * OUT_RPB;

    if (t < OUT_RPB * KSPLIT) {
        const int r = t >> 3;
        const int s = t & 7;
        const int row = row0 + r;
        const float* p = pn + ((size_t)s * ROWS + row) * H;
        float4 a = *reinterpret_cast<const float4*>(p);
        float4 b = *reinterpret_cast<const float4*>(p + 4);
        ps[r][s][0] = a.x; ps[r][s][1] = a.y; ps[r][s][2] = a.z; ps[r][s][3] = a.w;
        ps[r][s][4] = b.x; ps[r][s][5] = b.y; ps[r][s][6] = b.z; ps[r][s][7] = b.w;
        ps[r][s][8] = pd[(size_t)s * ROWS + row];
    }

    float4 w[H];
#pragma unroll
    for (int h = 0; h < H; ++h)
        w[h] = *reinterpret_cast<const float4*>(Wo + h * DIM + j);
    const float4 b4 = *reinterpret_cast<const float4*>(bo + j);

    __syncthreads();

    if (t < OUT_RPB) {
        float n[H] = {0.f, 0.f, 0.f, 0.f, 0.f, 0.f, 0.f, 0.f};
        float den = 0.0f;
#pragma unroll
        for (int s = 0; s < KSPLIT; ++s) {
#pragma unroll
            for (int h = 0; h < H; ++h) n[h] += ps[t][s][h];
            den += ps[t][s][8];
        }
        const float inv = 1.0f / den;
#pragma unroll
        for (int h = 0; h < H; ++h) a_sm[t][h] = n[h] * inv;
    }
    __syncthreads();

#pragma unroll
    for (int r = 0; r < OUT_RPB; ++r) {
        const int row = row0 + r;
        float4 o = b4;
#pragma unroll
        for (int h = 0; h < H; ++h) {
            float ah = a_sm[r][h];
            o.x = fmaf(ah, w[h].x, o.x);
            o.y = fmaf(ah, w[h].y, o.y);
            o.z = fmaf(ah, w[h].z, o.z);
            o.w = fmaf(ah, w[h].w, o.w);
        }
        *reinterpret_cast<float4*>(out + (size_t)row * DIM + j) = o;
    }
}

// ---------------------------------------------------------------------------
extern "C" void kernel_launch(void* const* d_in, const int* in_sizes, int n_in,
                              void* d_out, int out_size)
{
    const float* x       = (const float*)d_in[0];
    const float* context = (const float*)d_in[1];
    const float* Wq      = (const float*)d_in[2];
    const float* bq      = (const float*)d_in[3];
    const float* Wk      = (const float*)d_in[4];
    const float* bk      = (const float*)d_in[5];
    const float* Wv      = (const float*)d_in[6];
    const float* bv      = (const float*)d_in[7];
    const float* Wo      = (const float*)d_in[8];
    const float* bo      = (const float*)d_in[9];
    float* out = (float*)d_out;

    float* q_p;  cudaGetSymbolAddress((void**)&q_p,  g_q);
    float* k_p;  cudaGetSymbolAddress((void**)&k_p,  g_k);
    float* v_p;  cudaGetSymbolAddress((void**)&v_p,  g_v);
    float* pn_p; cudaGetSymbolAddress((void**)&pn_p, g_pn);
    float* pd_p; cudaGetSymbolAddress((void**)&pd_p, g_pd);

    proj_fused_kernel<<<3 * 256, 256>>>(x, context, Wq, bq, Wk, bk, Wv, bv,
                                        q_p, k_p, v_p);
    attn_part_kernel<<<BATCH * 16 * KSPLIT, 128>>>(q_p, k_p, v_p, pn_p, pd_p);
    outproj_kernel<<<ROWS / OUT_RPB, 256>>>(pn_p, pd_p, Wo, bo, out);
}

// round 13
// speedup vs baseline: 2.1829x; 2.1829x over previous
#include <cuda_runtime.h>
#include <cuda_bf16.h>
#include <cstdint>

// Problem constants
#define BATCH 8
#define SQ 2048
#define SK 2048
#define DIM 1024
#define H 8
#define ROWS (BATCH * SQ)   // 16384
#define KSPLIT 8
#define KS_LEN (SK / KSPLIT)  // 256

// Scratch (allocation-free: __device__ globals)
__device__ float g_q[ROWS * H];
__device__ float g_k[ROWS * H];
__device__ float g_v[ROWS * H];
__device__ float g_pn[KSPLIT * ROWS * H];  // partial numerators
__device__ float g_pd[KSPLIT * ROWS];      // partial denominators

typedef unsigned long long ull;

__device__ __forceinline__ ull ffma2(ull a, ull b, ull c) {
    ull d;
    asm("fma.rn.f32x2 %0, %1, %2, %3;" : "=l"(d) : "l"(a), "l"(b), "l"(c));
    return d;
}
__device__ __forceinline__ ull fmul2(ull a, ull b) {
    ull d;
    asm("mul.rn.f32x2 %0, %1, %2;" : "=l"(d) : "l"(a), "l"(b));
    return d;
}
__device__ __forceinline__ float f2_lo(ull a) { return __uint_as_float((unsigned)(a & 0xffffffffull)); }
__device__ __forceinline__ float f2_hi(ull a) { return __uint_as_float((unsigned)(a >> 32)); }
__device__ __forceinline__ ull f2_pack(float lo, float hi) {
    ull p;
    asm("mov.b64 %0, {%1, %2};" : "=l"(p) : "r"(__float_as_uint(lo)), "r"(__float_as_uint(hi)));
    return p;
}

__device__ __forceinline__ void cp_async16(uint32_t smem_dst, const void* gsrc) {
    asm volatile("cp.async.cg.shared.global [%0], [%1], 16;"
                 :: "r"(smem_dst), "l"(gsrc) : "memory");
}
__device__ __forceinline__ void cp_commit() {
    asm volatile("cp.async.commit_group;" ::: "memory");
}
#define CP_WAIT(n) asm volatile("cp.async.wait_group %0;" :: "n"(n) : "memory")

// ---------------------------------------------------------------------------
// Kernel 1: fused q/k/v projection. grid = 3 * 256 blocks x 512 threads.
//   path = blockIdx.x >> 8 selects (X, W, bias, Y). 64 rows/block,
//   4 rows/warp (16 warps). x is staged through smem with cp.async,
//   double-buffered in chunks of 128 floats x 64 rows (32 KB/buffer):
//   latency hiding costs ZERO registers, so acc[4][8] packed (64 regs)
//   fits with total ~90 regs -> no spill possible (the R6/R12 killer).
//   W transposed in smem (8 x 1024, no pad needed: LDS phase conflicts are
//   per-instruction, and lanes 0..7 span all 32 banks).
//   Dynamic smem: 32 KB (W) + 2 x 32 KB (x) = 96 KB, 1 block/SM.
// ---------------------------------------------------------------------------
#define PROJ_SMEM (32768 + 2 * 32768)
__global__ void __launch_bounds__(512, 1) proj_fused_kernel(
    const float* __restrict__ x, const float* __restrict__ ctx,
    const float* __restrict__ Wq, const float* __restrict__ bq,
    const float* __restrict__ Wk, const float* __restrict__ bk,
    const float* __restrict__ Wv, const float* __restrict__ bv,
    float* __restrict__ q, float* __restrict__ k, float* __restrict__ v)
{
    extern __shared__ float smem[];
    float* sw = smem;            // 8 x 1024 floats = 32 KB
    float* xs = smem + 8 * 1024; // 2 x (64 x 128) floats = 64 KB

    const int tid = threadIdx.x;
    const int warp = tid >> 5;
    const int lane = tid & 31;

    const int path = blockIdx.x >> 8;       // 0 = q, 1 = k, 2 = v
    const int blk  = blockIdx.x & 255;

    const float* X    = (path == 0) ? x  : ctx;
    const float* W    = (path == 0) ? Wq : (path == 1) ? Wk : Wv;
    const float* bias = (path == 0) ? bq : (path == 1) ? bk : bv;
    float*       Y    = (path == 0) ? q  : (path == 1) ? k  : v;

    // Stage W transposed: sw[h*1024 + d] = W[d*8 + h] (float4 global loads)
    for (int i = tid; i < DIM * 2; i += 512) {
        int d = i >> 1, hg = (i & 1) * 4;
        float4 w4 = *reinterpret_cast<const float4*>(W + d * H + hg);
        sw[(hg + 0) * 1024 + d] = w4.x;
        sw[(hg + 1) * 1024 + d] = w4.y;
        sw[(hg + 2) * 1024 + d] = w4.z;
        sw[(hg + 3) * 1024 + d] = w4.w;
    }
    float bias_lane = (lane < H) ? bias[lane] : 0.0f;

    const int row0 = blk * 64;
    const float* xbase = X + (size_t)row0 * DIM;
    const uint32_t xs_u32 = (uint32_t)__cvta_generic_to_shared(xs);

    // Stage chunk c (128 floats x 64 rows) into buffer c&1.
    // 2048 16B-segments / 512 threads = 4 cp.async per thread.
    auto stage = [&](int c) {
        const int buf = c & 1;
#pragma unroll
        for (int i = 0; i < 4; ++i) {
            int idx = tid + i * 512;       // 0..2047
            int row = idx >> 5;            // 0..63
            int seg = idx & 31;            // 16B units within 512B row-chunk
            const float* gsrc = xbase + (size_t)row * DIM + c * 128 + seg * 4;
            uint32_t dst = xs_u32 + (uint32_t)(buf * 8192 + row * 128 + seg * 4) * 4u;
            cp_async16(dst, gsrc);
        }
    };

    stage(0); cp_commit();
    __syncthreads();   // also covers W staging

    ull acc0[H], acc1[H], acc2[H], acc3[H];
#pragma unroll
    for (int h = 0; h < H; ++h) {
        acc0[h] = 0ull; acc1[h] = 0ull; acc2[h] = 0ull; acc3[h] = 0ull;
    }

    const int rbase = warp * 4;   // 4 rows per warp
    const int d = lane * 4;

#pragma unroll 1
    for (int u = 0; u < 8; ++u) {
        if (u < 7) { stage(u + 1); cp_commit(); CP_WAIT(1); }
        else       { CP_WAIT(0); }
        __syncthreads();   // chunk u visible to all warps

        const float* xb = xs + (u & 1) * 8192;
        ulonglong2 xv0 = *reinterpret_cast<const ulonglong2*>(xb + (rbase + 0) * 128 + d);
        ulonglong2 xv1 = *reinterpret_cast<const ulonglong2*>(xb + (rbase + 1) * 128 + d);
        ulonglong2 xv2 = *reinterpret_cast<const ulonglong2*>(xb + (rbase + 2) * 128 + d);
        ulonglong2 xv3 = *reinterpret_cast<const ulonglong2*>(xb + (rbase + 3) * 128 + d);

#pragma unroll
        for (int h = 0; h < H; ++h) {
            ulonglong2 wv = *reinterpret_cast<const ulonglong2*>(&sw[h * 1024 + u * 128 + d]);
            acc0[h] = ffma2(xv0.x, wv.x, acc0[h]);
            acc0[h] = ffma2(xv0.y, wv.y, acc0[h]);
            acc1[h] = ffma2(xv1.x, wv.x, acc1[h]);
            acc1[h] = ffma2(xv1.y, wv.y, acc1[h]);
            acc2[h] = ffma2(xv2.x, wv.x, acc2[h]);
            acc2[h] = ffma2(xv2.y, wv.y, acc2[h]);
            acc3[h] = ffma2(xv3.x, wv.x, acc3[h]);
            acc3[h] = ffma2(xv3.y, wv.y, acc3[h]);
        }

        __syncthreads();   // all warps done with buffer (u&1) before restage
    }

    // Reduce across lanes; lane h keeps head h's sum
#pragma unroll
    for (int r = 0; r < 4; ++r) {
        float keep = 0.0f;
#pragma unroll
        for (int h = 0; h < H; ++h) {
            ull a = (r == 0) ? acc0[h] : (r == 1) ? acc1[h] : (r == 2) ? acc2[h] : acc3[h];
            float s = f2_lo(a) + f2_hi(a);
            s += __shfl_xor_sync(0xffffffffu, s, 16);
            s += __shfl_xor_sync(0xffffffffu, s, 8);
            s += __shfl_xor_sync(0xffffffffu, s, 4);
            s += __shfl_xor_sync(0xffffffffu, s, 2);
            s += __shfl_xor_sync(0xffffffffu, s, 1);
            if (lane == h) keep = s;
        }
        if (lane < H) Y[(size_t)(row0 + rbase + r) * H + lane] = keep + bias_lane;
    }
}

// ---------------------------------------------------------------------------
// Kernel 2: attention partials with key-split.
//   grid = 8 batches x 16 qchunks x 8 ksplits = 1024 blocks x 128 threads.
//   One thread per query; each block covers 256 keys (tile in smem, 16 KB).
//   Softmax without max-subtraction -> split partials add exactly.
// ---------------------------------------------------------------------------
__global__ void __launch_bounds__(128) attn_part_kernel(
    const float* __restrict__ q, const float* __restrict__ k,
    const float* __restrict__ v, float* __restrict__ pn,
    float* __restrict__ pd)
{
    __shared__ float ks[KS_LEN * H];   // 8 KB
    __shared__ float vs[KS_LEN * H];   // 8 KB

    const int tid = threadIdx.x;
    const int bb = blockIdx.x >> 7;            // batch
    const int qc = (blockIdx.x >> 3) & 15;     // query chunk
    const int sp = blockIdx.x & 7;             // key split
    const int row = bb * SQ + qc * 128 + tid;
    const int kbase = bb * SK + sp * KS_LEN;

    // Cooperative tile load: 256 keys x 8 floats for k and v
    {
        const float4* kg = reinterpret_cast<const float4*>(k + (size_t)kbase * H);
        const float4* vg = reinterpret_cast<const float4*>(v + (size_t)kbase * H);
        float4* ks4 = reinterpret_cast<float4*>(ks);
        float4* vs4 = reinterpret_cast<float4*>(vs);
#pragma unroll
        for (int i = 0; i < (KS_LEN * H / 4) / 128; ++i) {
            ks4[tid + i * 128] = kg[tid + i * 128];
            vs4[tid + i * 128] = vg[tid + i * 128];
        }
    }

    // Query in registers as four f32x2 packs
    ulonglong2 qa = *reinterpret_cast<const ulonglong2*>(q + (size_t)row * H);
    ulonglong2 qb = *reinterpret_cast<const ulonglong2*>(q + (size_t)row * H + 4);
    const ull q01 = qa.x, q23 = qa.y, q45 = qb.x, q67 = qb.y;

    __syncthreads();

    ull acc0 = 0ull, acc1 = 0ull, acc2 = 0ull, acc3 = 0ull;
    float denom = 0.0f;

#pragma unroll 8
    for (int t = 0; t < KS_LEN; ++t) {
        ulonglong2 k0 = *reinterpret_cast<const ulonglong2*>(&ks[t * H]);
        ulonglong2 k1 = *reinterpret_cast<const ulonglong2*>(&ks[t * H + 4]);
        ull s2 = fmul2(q67, k1.y);
        s2 = ffma2(q45, k1.x, s2);
        s2 = ffma2(q23, k0.y, s2);
        s2 = ffma2(q01, k0.x, s2);
        float s = f2_lo(s2) + f2_hi(s2);
        float e = __expf(s);
        denom += e;
        ull e2 = f2_pack(e, e);
        ulonglong2 v0 = *reinterpret_cast<const ulonglong2*>(&vs[t * H]);
        ulonglong2 v1 = *reinterpret_cast<const ulonglong2*>(&vs[t * H + 4]);
        acc0 = ffma2(e2, v0.x, acc0);
        acc1 = ffma2(e2, v0.y, acc1);
        acc2 = ffma2(e2, v1.x, acc2);
        acc3 = ffma2(e2, v1.y, acc3);
    }

    float4 o0, o1;
    o0.x = f2_lo(acc0); o0.y = f2_hi(acc0);
    o0.z = f2_lo(acc1); o0.w = f2_hi(acc1);
    o1.x = f2_lo(acc2); o1.y = f2_hi(acc2);
    o1.z = f2_lo(acc3); o1.w = f2_hi(acc3);
    float* pnr = pn + ((size_t)sp * ROWS + row) * H;
    *reinterpret_cast<float4*>(pnr)     = o0;
    *reinterpret_cast<float4*>(pnr + 4) = o1;
    pd[(size_t)sp * ROWS + row] = denom;
}

// ---------------------------------------------------------------------------
// Kernel 3: combine split-K partials + output projection.
//   grid = 1024 blocks x 256 threads, 16 rows/block.
//   Fold parallelized: threads 0..127 each fetch one (row, split) partial
//   into smem; threads 0..15 then fold 8 splits from smem (LDS, not LDG).
//   All threads project with Wo slice in registers (8 x float4 per thread).
// ---------------------------------------------------------------------------
#define OUT_RPB 16
__global__ void __launch_bounds__(256) outproj_kernel(
    const float* __restrict__ pn, const float* __restrict__ pd,
    const float* __restrict__ Wo, const float* __restrict__ bo,
    float* __restrict__ out)
{
    __shared__ float ps[OUT_RPB][KSPLIT][12];  // 9 used, pad to 12
    __shared__ float a_sm[OUT_RPB][H];

    const int t = threadIdx.x;
    const int j = t * 4;
    const int row0 = blockIdx.x * OUT_RPB;

    if (t < OUT_RPB * KSPLIT) {
        const int r = t >> 3;
        const int s = t & 7;
        const int row = row0 + r;
        const float* p = pn + ((size_t)s * ROWS + row) * H;
        float4 a = *reinterpret_cast<const float4*>(p);
        float4 b = *reinterpret_cast<const float4*>(p + 4);
        ps[r][s][0] = a.x; ps[r][s][1] = a.y; ps[r][s][2] = a.z; ps[r][s][3] = a.w;
        ps[r][s][4] = b.x; ps[r][s][5] = b.y; ps[r][s][6] = b.z; ps[r][s][7] = b.w;
        ps[r][s][8] = pd[(size_t)s * ROWS + row];
    }

    float4 w[H];
#pragma unroll
    for (int h = 0; h < H; ++h)
        w[h] = *reinterpret_cast<const float4*>(Wo + h * DIM + j);
    const float4 b4 = *reinterpret_cast<const float4*>(bo + j);

    __syncthreads();

    if (t < OUT_RPB) {
        float n[H] = {0.f, 0.f, 0.f, 0.f, 0.f, 0.f, 0.f, 0.f};
        float den = 0.0f;
#pragma unroll
        for (int s = 0; s < KSPLIT; ++s) {
#pragma unroll
            for (int h = 0; h < H; ++h) n[h] += ps[t][s][h];
            den += ps[t][s][8];
        }
        const float inv = 1.0f / den;
#pragma unroll
        for (int h = 0; h < H; ++h) a_sm[t][h] = n[h] * inv;
    }
    __syncthreads();

#pragma unroll
    for (int r = 0; r < OUT_RPB; ++r) {
        const int row = row0 + r;
        float4 o = b4;
#pragma unroll
        for (int h = 0; h < H; ++h) {
            float ah = a_sm[r][h];
            o.x = fmaf(ah, w[h].x, o.x);
            o.y = fmaf(ah, w[h].y, o.y);
            o.z = fmaf(ah, w[h].z, o.z);
            o.w = fmaf(ah, w[h].w, o.w);
        }
        *reinterpret_cast<float4*>(out + (size_t)row * DIM + j) = o;
    }
}

// ---------------------------------------------------------------------------
extern "C" void kernel_launch(void* const* d_in, const int* in_sizes, int n_in,
                              void* d_out, int out_size)
{
    const float* x       = (const float*)d_in[0];
    const float* context = (const float*)d_in[1];
    const float* Wq      = (const float*)d_in[2];
    const float* bq      = (const float*)d_in[3];
    const float* Wk      = (const float*)d_in[4];
    const float* bk      = (const float*)d_in[5];
    const float* Wv      = (const float*)d_in[6];
    const float* bv      = (const float*)d_in[7];
    const float* Wo      = (const float*)d_in[8];
    const float* bo      = (const float*)d_in[9];
    float* out = (float*)d_out;

    float* q_p;  cudaGetSymbolAddress((void**)&q_p,  g_q);
    float* k_p;  cudaGetSymbolAddress((void**)&k_p,  g_k);
    float* v_p;  cudaGetSymbolAddress((void**)&v_p,  g_v);
    float* pn_p; cudaGetSymbolAddress((void**)&pn_p, g_pn);
    float* pd_p; cudaGetSymbolAddress((void**)&pd_p, g_pd);

    static bool attr_set = false;
    if (!attr_set) {
        cudaFuncSetAttribute(proj_fused_kernel,
                             cudaFuncAttributeMaxDynamicSharedMemorySize, PROJ_SMEM);
        attr_set = true;
    }

    proj_fused_kernel<<<3 * 256, 512, PROJ_SMEM>>>(x, context, Wq, bq, Wk, bk,
                                                   Wv, bv, q_p, k_p, v_p);
    attn_part_kernel<<<BATCH * 16 * KSPLIT, 128>>>(q_p, k_p, v_p, pn_p, pd_p);
    outproj_kernel<<<ROWS / OUT_RPB, 256>>>(pn_p, pd_p, Wo, bo, out);
}

// round 14
// speedup vs baseline: 2.3411x; 1.0724x over previous
#include <cuda_runtime.h>
#include <cuda_bf16.h>
#include <cstdint>

// Problem constants
#define BATCH 8
#define SQ 2048
#define SK 2048
#define DIM 1024
#define H 8
#define ROWS (BATCH * SQ)   // 16384
#define KSPLIT 8
#define KS_LEN (SK / KSPLIT)  // 256

// Scratch (allocation-free: __device__ globals)
__device__ float g_q[ROWS * H];
__device__ float g_k[ROWS * H];
__device__ float g_v[ROWS * H];
__device__ float g_pn[KSPLIT * ROWS * H];  // partial numerators
__device__ float g_pd[KSPLIT * ROWS];      // partial denominators

typedef unsigned long long ull;

__device__ __forceinline__ ull ffma2(ull a, ull b, ull c) {
    ull d;
    asm("fma.rn.f32x2 %0, %1, %2, %3;" : "=l"(d) : "l"(a), "l"(b), "l"(c));
    return d;
}
__device__ __forceinline__ ull fmul2(ull a, ull b) {
    ull d;
    asm("mul.rn.f32x2 %0, %1, %2;" : "=l"(d) : "l"(a), "l"(b));
    return d;
}
__device__ __forceinline__ float f2_lo(ull a) { return __uint_as_float((unsigned)(a & 0xffffffffull)); }
__device__ __forceinline__ float f2_hi(ull a) { return __uint_as_float((unsigned)(a >> 32)); }
__device__ __forceinline__ ull f2_pack(float lo, float hi) {
    ull p;
    asm("mov.b64 %0, {%1, %2};" : "=l"(p) : "r"(__float_as_uint(lo)), "r"(__float_as_uint(hi)));
    return p;
}

__device__ __forceinline__ void cp_async16(uint32_t smem_dst, const void* gsrc) {
    asm volatile("cp.async.cg.shared.global [%0], [%1], 16;"
                 :: "r"(smem_dst), "l"(gsrc) : "memory");
}
__device__ __forceinline__ void cp_commit() {
    asm volatile("cp.async.commit_group;" ::: "memory");
}
#define CP_WAIT(n) asm volatile("cp.async.wait_group %0;" :: "n"(n) : "memory")

// ---------------------------------------------------------------------------
// Kernel 1: fused q/k/v projection. grid = 3 * 512 = 1536 blocks x 256 threads.
//   path = blockIdx.x % 3 (INTERLEAVED so k/v blocks of the same row-range
//   run adjacently -> the v block's ctx read hits L2 behind the k block).
//   32 rows/block, 4 rows/warp (8 warps). x staged via cp.async,
//   double-buffered 16 KB chunks (128 floats x 32 rows).
//   Regs ~126, smem 64 KB -> TWO blocks/SM (R13 was reg-capped at one
//   512-thread block = whole 64K reg file; two independent barrier domains
//   fill each other's stage/barrier bubbles).
// ---------------------------------------------------------------------------
#define PROJ_SMEM (32768 + 2 * 16384)   // W 32 KB + 2 x 16 KB x-buffers
__global__ void __launch_bounds__(256, 2) proj_fused_kernel(
    const float* __restrict__ x, const float* __restrict__ ctx,
    const float* __restrict__ Wq, const float* __restrict__ bq,
    const float* __restrict__ Wk, const float* __restrict__ bk,
    const float* __restrict__ Wv, const float* __restrict__ bv,
    float* __restrict__ q, float* __restrict__ k, float* __restrict__ v)
{
    extern __shared__ float smem[];
    float* sw = smem;            // 8 x 1024 floats = 32 KB
    float* xs = smem + 8 * 1024; // 2 x (32 x 128) floats = 32 KB

    const int tid = threadIdx.x;
    const int warp = tid >> 5;
    const int lane = tid & 31;

    const int path = blockIdx.x % 3;        // 0 = q, 1 = k, 2 = v (interleaved)
    const int blk  = blockIdx.x / 3;        // 0..511

    const float* X    = (path == 0) ? x  : ctx;
    const float* W    = (path == 0) ? Wq : (path == 1) ? Wk : Wv;
    const float* bias = (path == 0) ? bq : (path == 1) ? bk : bv;
    float*       Y    = (path == 0) ? q  : (path == 1) ? k  : v;

    // Stage W transposed: sw[h*1024 + d] = W[d*8 + h] (float4 global loads)
    for (int i = tid; i < DIM * 2; i += 256) {
        int d = i >> 1, hg = (i & 1) * 4;
        float4 w4 = *reinterpret_cast<const float4*>(W + d * H + hg);
        sw[(hg + 0) * 1024 + d] = w4.x;
        sw[(hg + 1) * 1024 + d] = w4.y;
        sw[(hg + 2) * 1024 + d] = w4.z;
        sw[(hg + 3) * 1024 + d] = w4.w;
    }
    float bias_lane = (lane < H) ? bias[lane] : 0.0f;

    const int row0 = blk * 32;
    const float* xbase = X + (size_t)row0 * DIM;
    const uint32_t xs_u32 = (uint32_t)__cvta_generic_to_shared(xs);

    // Stage chunk c (128 floats x 32 rows = 16 KB) into buffer c&1.
    // 1024 16B-segments / 256 threads = 4 cp.async per thread.
    auto stage = [&](int c) {
        const int buf = c & 1;
#pragma unroll
        for (int i = 0; i < 4; ++i) {
            int idx = tid + i * 256;       // 0..1023
            int row = idx >> 5;            // 0..31
            int seg = idx & 31;            // 16B units within 512B row-chunk
            const float* gsrc = xbase + (size_t)row * DIM + c * 128 + seg * 4;
            uint32_t dst = xs_u32 + (uint32_t)(buf * 4096 + row * 128 + seg * 4) * 4u;
            cp_async16(dst, gsrc);
        }
    };

    stage(0); cp_commit();
    __syncthreads();   // also covers W staging

    ull acc0[H], acc1[H], acc2[H], acc3[H];
#pragma unroll
    for (int h = 0; h < H; ++h) {
        acc0[h] = 0ull; acc1[h] = 0ull; acc2[h] = 0ull; acc3[h] = 0ull;
    }

    const int rbase = warp * 4;   // 4 rows per warp (8 warps x 4 = 32 rows)
    const int d = lane * 4;

#pragma unroll 1
    for (int u = 0; u < 8; ++u) {
        if (u < 7) { stage(u + 1); cp_commit(); CP_WAIT(1); }
        else       { CP_WAIT(0); }
        __syncthreads();   // chunk u visible to all warps

        const float* xb = xs + (u & 1) * 4096;
        ulonglong2 xv0 = *reinterpret_cast<const ulonglong2*>(xb + (rbase + 0) * 128 + d);
        ulonglong2 xv1 = *reinterpret_cast<const ulonglong2*>(xb + (rbase + 1) * 128 + d);
        ulonglong2 xv2 = *reinterpret_cast<const ulonglong2*>(xb + (rbase + 2) * 128 + d);
        ulonglong2 xv3 = *reinterpret_cast<const ulonglong2*>(xb + (rbase + 3) * 128 + d);

#pragma unroll
        for (int h = 0; h < H; ++h) {
            ulonglong2 wv = *reinterpret_cast<const ulonglong2*>(&sw[h * 1024 + u * 128 + d]);
            acc0[h] = ffma2(xv0.x, wv.x, acc0[h]);
            acc0[h] = ffma2(xv0.y, wv.y, acc0[h]);
            acc1[h] = ffma2(xv1.x, wv.x, acc1[h]);
            acc1[h] = ffma2(xv1.y, wv.y, acc1[h]);
            acc2[h] = ffma2(xv2.x, wv.x, acc2[h]);
            acc2[h] = ffma2(xv2.y, wv.y, acc2[h]);
            acc3[h] = ffma2(xv3.x, wv.x, acc3[h]);
            acc3[h] = ffma2(xv3.y, wv.y, acc3[h]);
        }

        __syncthreads();   // all warps done with buffer (u&1) before restage
    }

    // Reduce across lanes; lane h keeps head h's sum
#pragma unroll
    for (int r = 0; r < 4; ++r) {
        float keep = 0.0f;
#pragma unroll
        for (int h = 0; h < H; ++h) {
            ull a = (r == 0) ? acc0[h] : (r == 1) ? acc1[h] : (r == 2) ? acc2[h] : acc3[h];
            float s = f2_lo(a) + f2_hi(a);
            s += __shfl_xor_sync(0xffffffffu, s, 16);
            s += __shfl_xor_sync(0xffffffffu, s, 8);
            s += __shfl_xor_sync(0xffffffffu, s, 4);
            s += __shfl_xor_sync(0xffffffffu, s, 2);
            s += __shfl_xor_sync(0xffffffffu, s, 1);
            if (lane == h) keep = s;
        }
        if (lane < H) Y[(size_t)(row0 + rbase + r) * H + lane] = keep + bias_lane;
    }
}

// ---------------------------------------------------------------------------
// Kernel 2: attention partials with key-split.
//   grid = 8 batches x 16 qchunks x 8 ksplits = 1024 blocks x 128 threads.
//   One thread per query; each block covers 256 keys (tile in smem, 16 KB).
//   Softmax without max-subtraction -> split partials add exactly.
// ---------------------------------------------------------------------------
__global__ void __launch_bounds__(128) attn_part_kernel(
    const float* __restrict__ q, const float* __restrict__ k,
    const float* __restrict__ v, float* __restrict__ pn,
    float* __restrict__ pd)
{
    __shared__ float ks[KS_LEN * H];   // 8 KB
    __shared__ float vs[KS_LEN * H];   // 8 KB

    const int tid = threadIdx.x;
    const int bb = blockIdx.x >> 7;            // batch
    const int qc = (blockIdx.x >> 3) & 15;     // query chunk
    const int sp = blockIdx.x & 7;             // key split
    const int row = bb * SQ + qc * 128 + tid;
    const int kbase = bb * SK + sp * KS_LEN;

    // Cooperative tile load: 256 keys x 8 floats for k and v
    {
        const float4* kg = reinterpret_cast<const float4*>(k + (size_t)kbase * H);
        const float4* vg = reinterpret_cast<const float4*>(v + (size_t)kbase * H);
        float4* ks4 = reinterpret_cast<float4*>(ks);
        float4* vs4 = reinterpret_cast<float4*>(vs);
#pragma unroll
        for (int i = 0; i < (KS_LEN * H / 4) / 128; ++i) {
            ks4[tid + i * 128] = kg[tid + i * 128];
            vs4[tid + i * 128] = vg[tid + i * 128];
        }
    }

    // Query in registers as four f32x2 packs
    ulonglong2 qa = *reinterpret_cast<const ulonglong2*>(q + (size_t)row * H);
    ulonglong2 qb = *reinterpret_cast<const ulonglong2*>(q + (size_t)row * H + 4);
    const ull q01 = qa.x, q23 = qa.y, q45 = qb.x, q67 = qb.y;

    __syncthreads();

    ull acc0 = 0ull, acc1 = 0ull, acc2 = 0ull, acc3 = 0ull;
    float denom = 0.0f;

#pragma unroll 8
    for (int t = 0; t < KS_LEN; ++t) {
        ulonglong2 k0 = *reinterpret_cast<const ulonglong2*>(&ks[t * H]);
        ulonglong2 k1 = *reinterpret_cast<const ulonglong2*>(&ks[t * H + 4]);
        ull s2 = fmul2(q67, k1.y);
        s2 = ffma2(q45, k1.x, s2);
        s2 = ffma2(q23, k0.y, s2);
        s2 = ffma2(q01, k0.x, s2);
        float s = f2_lo(s2) + f2_hi(s2);
        float e = __expf(s);
        denom += e;
        ull e2 = f2_pack(e, e);
        ulonglong2 v0 = *reinterpret_cast<const ulonglong2*>(&vs[t * H]);
        ulonglong2 v1 = *reinterpret_cast<const ulonglong2*>(&vs[t * H + 4]);
        acc0 = ffma2(e2, v0.x, acc0);
        acc1 = ffma2(e2, v0.y, acc1);
        acc2 = ffma2(e2, v1.x, acc2);
        acc3 = ffma2(e2, v1.y, acc3);
    }

    float4 o0, o1;
    o0.x = f2_lo(acc0); o0.y = f2_hi(acc0);
    o0.z = f2_lo(acc1); o0.w = f2_hi(acc1);
    o1.x = f2_lo(acc2); o1.y = f2_hi(acc2);
    o1.z = f2_lo(acc3); o1.w = f2_hi(acc3);
    float* pnr = pn + ((size_t)sp * ROWS + row) * H;
    *reinterpret_cast<float4*>(pnr)     = o0;
    *reinterpret_cast<float4*>(pnr + 4) = o1;
    pd[(size_t)sp * ROWS + row] = denom;
}

// ---------------------------------------------------------------------------
// Kernel 3: combine split-K partials + output projection.
//   grid = 1024 blocks x 256 threads, 16 rows/block.
//   Fold parallelized: threads 0..127 each fetch one (row, split) partial
//   into smem; threads 0..15 then fold 8 splits from smem (LDS, not LDG).
//   All threads project with Wo slice in registers (8 x float4 per thread).
// ---------------------------------------------------------------------------
#define OUT_RPB 16
__global__ void __launch_bounds__(256) outproj_kernel(
    const float* __restrict__ pn, const float* __restrict__ pd,
    const float* __restrict__ Wo, const float* __restrict__ bo,
    float* __restrict__ out)
{
    __shared__ float ps[OUT_RPB][KSPLIT][12];  // 9 used, pad to 12
    __shared__ float a_sm[OUT_RPB][H];

    const int t = threadIdx.x;
    const int j = t * 4;
    const int row0 = blockIdx.x * OUT_RPB;

    if (t < OUT_RPB * KSPLIT) {
        const int r = t >> 3;
        const int s = t & 7;
        const int row = row0 + r;
        const float* p = pn + ((size_t)s * ROWS + row) * H;
        float4 a = *reinterpret_cast<const float4*>(p);
        float4 b = *reinterpret_cast<const float4*>(p + 4);
        ps[r][s][0] = a.x; ps[r][s][1] = a.y; ps[r][s][2] = a.z; ps[r][s][3] = a.w;
        ps[r][s][4] = b.x; ps[r][s][5] = b.y; ps[r][s][6] = b.z; ps[r][s][7] = b.w;
        ps[r][s][8] = pd[(size_t)s * ROWS + row];
    }

    float4 w[H];
#pragma unroll
    for (int h = 0; h < H; ++h)
        w[h] = *reinterpret_cast<const float4*>(Wo + h * DIM + j);
    const float4 b4 = *reinterpret_cast<const float4*>(bo + j);

    __syncthreads();

    if (t < OUT_RPB) {
        float n[H] = {0.f, 0.f, 0.f, 0.f, 0.f, 0.f, 0.f, 0.f};
        float den = 0.0f;
#pragma unroll
        for (int s = 0; s < KSPLIT; ++s) {
#pragma unroll
            for (int h = 0; h < H; ++h) n[h] += ps[t][s][h];
            den += ps[t][s][8];
        }
        const float inv = 1.0f / den;
#pragma unroll
        for (int h = 0; h < H; ++h) a_sm[t][h] = n[h] * inv;
    }
    __syncthreads();

#pragma unroll
    for (int r = 0; r < OUT_RPB; ++r) {
        const int row = row0 + r;
        float4 o = b4;
#pragma unroll
        for (int h = 0; h < H; ++h) {
            float ah = a_sm[r][h];
            o.x = fmaf(ah, w[h].x, o.x);
            o.y = fmaf(ah, w[h].y, o.y);
            o.z = fmaf(ah, w[h].z, o.z);
            o.w = fmaf(ah, w[h].w, o.w);
        }
        *reinterpret_cast<float4*>(out + (size_t)row * DIM + j) = o;
    }
}

// ---------------------------------------------------------------------------
extern "C" void kernel_launch(void* const* d_in, const int* in_sizes, int n_in,
                              void* d_out, int out_size)
{
    const float* x       = (const float*)d_in[0];
    const float* context = (const float*)d_in[1];
    const float* Wq      = (const float*)d_in[2];
    const float* bq      = (const float*)d_in[3];
    const float* Wk      = (const float*)d_in[4];
    const float* bk      = (const float*)d_in[5];
    const float* Wv      = (const float*)d_in[6];
    const float* bv      = (const float*)d_in[7];
    const float* Wo      = (const float*)d_in[8];
    const float* bo      = (const float*)d_in[9];
    float* out = (float*)d_out;

    float* q_p;  cudaGetSymbolAddress((void**)&q_p,  g_q);
    float* k_p;  cudaGetSymbolAddress((void**)&k_p,  g_k);
    float* v_p;  cudaGetSymbolAddress((void**)&v_p,  g_v);
    float* pn_p; cudaGetSymbolAddress((void**)&pn_p, g_pn);
    float* pd_p; cudaGetSymbolAddress((void**)&pd_p, g_pd);

    cudaFuncSetAttribute(proj_fused_kernel,
                         cudaFuncAttributeMaxDynamicSharedMemorySize, PROJ_SMEM);

    proj_fused_kernel<<<3 * 512, 256, PROJ_SMEM>>>(x, context, Wq, bq, Wk, bk,
                                                   Wv, bv, q_p, k_p, v_p);
    attn_part_kernel<<<BATCH * 16 * KSPLIT, 128>>>(q_p, k_p, v_p, pn_p, pd_p);
    outproj_kernel<<<ROWS / OUT_RPB, 256>>>(pn_p, pd_p, Wo, bo, out);
}

// round 15
// speedup vs baseline: 2.5117x; 1.0729x over previous
#include <cuda_runtime.h>
#include <cuda_bf16.h>
#include <cstdint>

// Problem constants
#define BATCH 8
#define SQ 2048
#define SK 2048
#define DIM 1024
#define H 8
#define ROWS (BATCH * SQ)   // 16384
#define KSPLIT 8
#define KS_LEN (SK / KSPLIT)  // 256

// Scratch (allocation-free: __device__ globals)
__device__ float g_q[ROWS * H];
__device__ float g_k[ROWS * H];
__device__ float g_v[ROWS * H];
__device__ float g_pn[KSPLIT * ROWS * H];  // partial numerators
__device__ float g_pd[KSPLIT * ROWS];      // partial denominators

typedef unsigned long long ull;

__device__ __forceinline__ ull ffma2(ull a, ull b, ull c) {
    ull d;
    asm("fma.rn.f32x2 %0, %1, %2, %3;" : "=l"(d) : "l"(a), "l"(b), "l"(c));
    return d;
}
__device__ __forceinline__ ull fmul2(ull a, ull b) {
    ull d;
    asm("mul.rn.f32x2 %0, %1, %2;" : "=l"(d) : "l"(a), "l"(b));
    return d;
}
__device__ __forceinline__ float f2_lo(ull a) { return __uint_as_float((unsigned)(a & 0xffffffffull)); }
__device__ __forceinline__ float f2_hi(ull a) { return __uint_as_float((unsigned)(a >> 32)); }
__device__ __forceinline__ ull f2_pack(float lo, float hi) {
    ull p;
    asm("mov.b64 %0, {%1, %2};" : "=l"(p) : "r"(__float_as_uint(lo)), "r"(__float_as_uint(hi)));
    return p;
}

__device__ __forceinline__ void cp_async16(uint32_t smem_dst, const void* gsrc) {
    asm volatile("cp.async.cg.shared.global [%0], [%1], 16;"
                 :: "r"(smem_dst), "l"(gsrc) : "memory");
}
__device__ __forceinline__ void cp_commit() {
    asm volatile("cp.async.commit_group;" ::: "memory");
}
#define CP_WAIT(n) asm volatile("cp.async.wait_group %0;" :: "n"(n) : "memory")

// ---------------------------------------------------------------------------
// Kernel 1: fused q/k/v projection. grid = 3 * 512 = 1536 blocks x 256 threads.
//   path = blockIdx.x % 3 (interleaved: v's ctx read L2-hits behind k's).
//   32 rows/block, 4 rows/warp (8 warps). x staged via cp.async into FOUR
//   16 KB buffers with prefetch distance 2 (stage u+2 while computing u):
//   CP_WAIT sees ~2 compute-rounds of slack >= DRAM latency -> no exposure.
//   4 buffers make the single-barrier scheme safe: stage(u+2) writes buf
//   (u+2)&3, which conflicts only with chunk u-2, finished by ALL warps
//   before the iter-(u-1) barrier. ONE __syncthreads per chunk (was 2).
//   Regs ~125, smem 32 KB (W) + 64 KB (x) = 96 KB -> 2 blocks/SM.
// ---------------------------------------------------------------------------
#define PROJ_SMEM (32768 + 4 * 16384)
__global__ void __launch_bounds__(256, 2) proj_fused_kernel(
    const float* __restrict__ x, const float* __restrict__ ctx,
    const float* __restrict__ Wq, const float* __restrict__ bq,
    const float* __restrict__ Wk, const float* __restrict__ bk,
    const float* __restrict__ Wv, const float* __restrict__ bv,
    float* __restrict__ q, float* __restrict__ k, float* __restrict__ v)
{
    extern __shared__ float smem[];
    float* sw = smem;            // 8 x 1024 floats = 32 KB
    float* xs = smem + 8 * 1024; // 4 x (32 x 128) floats = 64 KB

    const int tid = threadIdx.x;
    const int warp = tid >> 5;
    const int lane = tid & 31;

    const int path = blockIdx.x % 3;        // 0 = q, 1 = k, 2 = v (interleaved)
    const int blk  = blockIdx.x / 3;        // 0..511

    const float* X    = (path == 0) ? x  : ctx;
    const float* W    = (path == 0) ? Wq : (path == 1) ? Wk : Wv;
    const float* bias = (path == 0) ? bq : (path == 1) ? bk : bv;
    float*       Y    = (path == 0) ? q  : (path == 1) ? k  : v;

    // Stage W transposed: sw[h*1024 + d] = W[d*8 + h] (float4 global loads)
    for (int i = tid; i < DIM * 2; i += 256) {
        int d = i >> 1, hg = (i & 1) * 4;
        float4 w4 = *reinterpret_cast<const float4*>(W + d * H + hg);
        sw[(hg + 0) * 1024 + d] = w4.x;
        sw[(hg + 1) * 1024 + d] = w4.y;
        sw[(hg + 2) * 1024 + d] = w4.z;
        sw[(hg + 3) * 1024 + d] = w4.w;
    }
    float bias_lane = (lane < H) ? bias[lane] : 0.0f;

    const int row0 = blk * 32;
    const uint32_t xs_u32 = (uint32_t)__cvta_generic_to_shared(xs);

    // Hoisted stage addressing: thread covers 4 fixed (row, seg) slots.
    //   idx = tid + i*256 in [0,1024): row = idx>>5 (0..31), seg = idx&31.
    const float* gsrc_b[4];
    uint32_t     dst_b[4];
#pragma unroll
    for (int i = 0; i < 4; ++i) {
        int idx = tid + i * 256;
        int row = idx >> 5;
        int seg = idx & 31;
        gsrc_b[i] = X + (size_t)(row0 + row) * DIM + seg * 4;
        dst_b[i]  = xs_u32 + (uint32_t)(row * 128 + seg * 4) * 4u;
    }

    auto stage = [&](int c) {
        const uint32_t boff = (uint32_t)(c & 3) * 16384u;  // 4096 floats * 4 B
#pragma unroll
        for (int i = 0; i < 4; ++i)
            cp_async16(dst_b[i] + boff, gsrc_b[i] + c * 128);
    };

    stage(0); cp_commit();
    stage(1); cp_commit();

    ull acc0[H], acc1[H], acc2[H], acc3[H];
#pragma unroll
    for (int h = 0; h < H; ++h) {
        acc0[h] = 0ull; acc1[h] = 0ull; acc2[h] = 0ull; acc3[h] = 0ull;
    }

    const int rbase = warp * 4;   // 4 rows per warp (8 warps x 4 = 32 rows)
    const int d = lane * 4;

#pragma unroll 1
    for (int u = 0; u < 8; ++u) {
        if (u < 6)      { stage(u + 2); cp_commit(); CP_WAIT(2); }
        else if (u == 6) { CP_WAIT(1); }
        else             { CP_WAIT(0); }
        __syncthreads();   // chunk u (and, at u=0, W) visible to all warps

        const float* xb = xs + (u & 3) * 4096;
        ulonglong2 xv0 = *reinterpret_cast<const ulonglong2*>(xb + (rbase + 0) * 128 + d);
        ulonglong2 xv1 = *reinterpret_cast<const ulonglong2*>(xb + (rbase + 1) * 128 + d);
        ulonglong2 xv2 = *reinterpret_cast<const ulonglong2*>(xb + (rbase + 2) * 128 + d);
        ulonglong2 xv3 = *reinterpret_cast<const ulonglong2*>(xb + (rbase + 3) * 128 + d);

#pragma unroll
        for (int h = 0; h < H; ++h) {
            ulonglong2 wv = *reinterpret_cast<const ulonglong2*>(&sw[h * 1024 + u * 128 + d]);
            acc0[h] = ffma2(xv0.x, wv.x, acc0[h]);
            acc0[h] = ffma2(xv0.y, wv.y, acc0[h]);
            acc1[h] = ffma2(xv1.x, wv.x, acc1[h]);
            acc1[h] = ffma2(xv1.y, wv.y, acc1[h]);
            acc2[h] = ffma2(xv2.x, wv.x, acc2[h]);
            acc2[h] = ffma2(xv2.y, wv.y, acc2[h]);
            acc3[h] = ffma2(xv3.x, wv.x, acc3[h]);
            acc3[h] = ffma2(xv3.y, wv.y, acc3[h]);
        }
        // No trailing barrier: next writes target buf (u+3)&3, whose last
        // readers (chunk u-1... wait: chunk (u+3)-4 = u-1) are fenced by the
        // barrier at the TOP of iteration u+1 before stage(u+3) is issued.
    }

    // Reduce across lanes; lane h keeps head h's sum
#pragma unroll
    for (int r = 0; r < 4; ++r) {
        float keep = 0.0f;
#pragma unroll
        for (int h = 0; h < H; ++h) {
            ull a = (r == 0) ? acc0[h] : (r == 1) ? acc1[h] : (r == 2) ? acc2[h] : acc3[h];
            float s = f2_lo(a) + f2_hi(a);
            s += __shfl_xor_sync(0xffffffffu, s, 16);
            s += __shfl_xor_sync(0xffffffffu, s, 8);
            s += __shfl_xor_sync(0xffffffffu, s, 4);
            s += __shfl_xor_sync(0xffffffffu, s, 2);
            s += __shfl_xor_sync(0xffffffffu, s, 1);
            if (lane == h) keep = s;
        }
        if (lane < H) Y[(size_t)(row0 + rbase + r) * H + lane] = keep + bias_lane;
    }
}

// ---------------------------------------------------------------------------
// Kernel 2: attention partials with key-split.
//   grid = 8 batches x 16 qchunks x 8 ksplits = 1024 blocks x 128 threads.
//   One thread per query; each block covers 256 keys (tile in smem, 16 KB).
//   Softmax without max-subtraction -> split partials add exactly.
// ---------------------------------------------------------------------------
__global__ void __launch_bounds__(128) attn_part_kernel(
    const float* __restrict__ q, const float* __restrict__ k,
    const float* __restrict__ v, float* __restrict__ pn,
    float* __restrict__ pd)
{
    __shared__ float ks[KS_LEN * H];   // 8 KB
    __shared__ float vs[KS_LEN * H];   // 8 KB

    const int tid = threadIdx.x;
    const int bb = blockIdx.x >> 7;            // batch
    const int qc = (blockIdx.x >> 3) & 15;     // query chunk
    const int sp = blockIdx.x & 7;             // key split
    const int row = bb * SQ + qc * 128 + tid;
    const int kbase = bb * SK + sp * KS_LEN;

    // Cooperative tile load: 256 keys x 8 floats for k and v
    {
        const float4* kg = reinterpret_cast<const float4*>(k + (size_t)kbase * H);
        const float4* vg = reinterpret_cast<const float4*>(v + (size_t)kbase * H);
        float4* ks4 = reinterpret_cast<float4*>(ks);
        float4* vs4 = reinterpret_cast<float4*>(vs);
#pragma unroll
        for (int i = 0; i < (KS_LEN * H / 4) / 128; ++i) {
            ks4[tid + i * 128] = kg[tid + i * 128];
            vs4[tid + i * 128] = vg[tid + i * 128];
        }
    }

    // Query in registers as four f32x2 packs
    ulonglong2 qa = *reinterpret_cast<const ulonglong2*>(q + (size_t)row * H);
    ulonglong2 qb = *reinterpret_cast<const ulonglong2*>(q + (size_t)row * H + 4);
    const ull q01 = qa.x, q23 = qa.y, q45 = qb.x, q67 = qb.y;

    __syncthreads();

    ull acc0 = 0ull, acc1 = 0ull, acc2 = 0ull, acc3 = 0ull;
    float denom = 0.0f;

#pragma unroll 8
    for (int t = 0; t < KS_LEN; ++t) {
        ulonglong2 k0 = *reinterpret_cast<const ulonglong2*>(&ks[t * H]);
        ulonglong2 k1 = *reinterpret_cast<const ulonglong2*>(&ks[t * H + 4]);
        ull s2 = fmul2(q67, k1.y);
        s2 = ffma2(q45, k1.x, s2);
        s2 = ffma2(q23, k0.y, s2);
        s2 = ffma2(q01, k0.x, s2);
        float s = f2_lo(s2) + f2_hi(s2);
        float e = __expf(s);
        denom += e;
        ull e2 = f2_pack(e, e);
        ulonglong2 v0 = *reinterpret_cast<const ulonglong2*>(&vs[t * H]);
        ulonglong2 v1 = *reinterpret_cast<const ulonglong2*>(&vs[t * H + 4]);
        acc0 = ffma2(e2, v0.x, acc0);
        acc1 = ffma2(e2, v0.y, acc1);
        acc2 = ffma2(e2, v1.x, acc2);
        acc3 = ffma2(e2, v1.y, acc3);
    }

    float4 o0, o1;
    o0.x = f2_lo(acc0); o0.y = f2_hi(acc0);
    o0.z = f2_lo(acc1); o0.w = f2_hi(acc1);
    o1.x = f2_lo(acc2); o1.y = f2_hi(acc2);
    o1.z = f2_lo(acc3); o1.w = f2_hi(acc3);
    float* pnr = pn + ((size_t)sp * ROWS + row) * H;
    *reinterpret_cast<float4*>(pnr)     = o0;
    *reinterpret_cast<float4*>(pnr + 4) = o1;
    pd[(size_t)sp * ROWS + row] = denom;
}

// ---------------------------------------------------------------------------
// Kernel 3: combine split-K partials + output projection.
//   grid = 1024 blocks x 256 threads, 16 rows/block.
//   Fold parallelized: threads 0..127 each fetch one (row, split) partial
//   into smem; threads 0..15 then fold 8 splits from smem (LDS, not LDG).
//   All threads project with Wo slice in registers (8 x float4 per thread).
// ---------------------------------------------------------------------------
#define OUT_RPB 16
__global__ void __launch_bounds__(256) outproj_kernel(
    const float* __restrict__ pn, const float* __restrict__ pd,
    const float* __restrict__ Wo, const float* __restrict__ bo,
    float* __restrict__ out)
{
    __shared__ float ps[OUT_RPB][KSPLIT][12];  // 9 used, pad to 12
    __shared__ float a_sm[OUT_RPB][H];

    const int t = threadIdx.x;
    const int j = t * 4;
    const int row0 = blockIdx.x * OUT_RPB;

    if (t < OUT_RPB * KSPLIT) {
        const int r = t >> 3;
        const int s = t & 7;
        const int row = row0 + r;
        const float* p = pn + ((size_t)s * ROWS + row) * H;
        float4 a = *reinterpret_cast<const float4*>(p);
        float4 b = *reinterpret_cast<const float4*>(p + 4);
        ps[r][s][0] = a.x; ps[r][s][1] = a.y; ps[r][s][2] = a.z; ps[r][s][3] = a.w;
        ps[r][s][4] = b.x; ps[r][s][5] = b.y; ps[r][s][6] = b.z; ps[r][s][7] = b.w;
        ps[r][s][8] = pd[(size_t)s * ROWS + row];
    }

    float4 w[H];
#pragma unroll
    for (int h = 0; h < H; ++h)
        w[h] = *reinterpret_cast<const float4*>(Wo + h * DIM + j);
    const float4 b4 = *reinterpret_cast<const float4*>(bo + j);

    __syncthreads();

    if (t < OUT_RPB) {
        float n[H] = {0.f, 0.f, 0.f, 0.f, 0.f, 0.f, 0.f, 0.f};
        float den = 0.0f;
#pragma unroll
        for (int s = 0; s < KSPLIT; ++s) {
#pragma unroll
            for (int h = 0; h < H; ++h) n[h] += ps[t][s][h];
            den += ps[t][s][8];
        }
        const float inv = 1.0f / den;
#pragma unroll
        for (int h = 0; h < H; ++h) a_sm[t][h] = n[h] * inv;
    }
    __syncthreads();

#pragma unroll
    for (int r = 0; r < OUT_RPB; ++r) {
        const int row = row0 + r;
        float4 o = b4;
#pragma unroll
        for (int h = 0; h < H; ++h) {
            float ah = a_sm[r][h];
            o.x = fmaf(ah, w[h].x, o.x);
            o.y = fmaf(ah, w[h].y, o.y);
            o.z = fmaf(ah, w[h].z, o.z);
            o.w = fmaf(ah, w[h].w, o.w);
        }
        *reinterpret_cast<float4*>(out + (size_t)row * DIM + j) = o;
    }
}

// ---------------------------------------------------------------------------
extern "C" void kernel_launch(void* const* d_in, const int* in_sizes, int n_in,
                              void* d_out, int out_size)
{
    const float* x       = (const float*)d_in[0];
    const float* context = (const float*)d_in[1];
    const float* Wq      = (const float*)d_in[2];
    const float* bq      = (const float*)d_in[3];
    const float* Wk      = (const float*)d_in[4];
    const float* bk      = (const float*)d_in[5];
    const float* Wv      = (const float*)d_in[6];
    const float* bv      = (const float*)d_in[7];
    const float* Wo      = (const float*)d_in[8];
    const float* bo      = (const float*)d_in[9];
    float* out = (float*)d_out;

    float* q_p;  cudaGetSymbolAddress((void**)&q_p,  g_q);
    float* k_p;  cudaGetSymbolAddress((void**)&k_p,  g_k);
    float* v_p;  cudaGetSymbolAddress((void**)&v_p,  g_v);
    float* pn_p; cudaGetSymbolAddress((void**)&pn_p, g_pn);
    float* pd_p; cudaGetSymbolAddress((void**)&pd_p, g_pd);

    cudaFuncSetAttribute(proj_fused_kernel,
                         cudaFuncAttributeMaxDynamicSharedMemorySize, PROJ_SMEM);

    proj_fused_kernel<<<3 * 512, 256, PROJ_SMEM>>>(x, context, Wq, bq, Wk, bk,
                                                   Wv, bv, q_p, k_p, v_p);
    attn_part_kernel<<<BATCH * 16 * KSPLIT, 128>>>(q_p, k_p, v_p, pn_p, pd_p);
    outproj_kernel<<<ROWS / OUT_RPB, 256>>>(pn_p, pd_p, Wo, bo, out);
}

// round 17
// speedup vs baseline: 2.6390x; 1.0507x over previous
#include <cuda_runtime.h>
#include <cuda_bf16.h>
#include <cstdint>

// Problem constants
#define BATCH 8
#define SQ 2048
#define SK 2048
#define DIM 1024
#define H 8
#define ROWS (BATCH * SQ)   // 16384
#define KSPLIT 8
#define KS_LEN (SK / KSPLIT)  // 256

// Scratch (allocation-free: __device__ globals)
__device__ float g_q[ROWS * H];
__device__ float g_k[ROWS * H];
__device__ float g_v[ROWS * H];
__device__ float g_pn[KSPLIT * ROWS * H];  // partial numerators
__device__ float g_pd[KSPLIT * ROWS];      // partial denominators

typedef unsigned long long ull;

__device__ __forceinline__ ull ffma2(ull a, ull b, ull c) {
    ull d;
    asm("fma.rn.f32x2 %0, %1, %2, %3;" : "=l"(d) : "l"(a), "l"(b), "l"(c));
    return d;
}
__device__ __forceinline__ ull fmul2(ull a, ull b) {
    ull d;
    asm("mul.rn.f32x2 %0, %1, %2;" : "=l"(d) : "l"(a), "l"(b));
    return d;
}
__device__ __forceinline__ float f2_lo(ull a) { return __uint_as_float((unsigned)(a & 0xffffffffull)); }
__device__ __forceinline__ float f2_hi(ull a) { return __uint_as_float((unsigned)(a >> 32)); }
__device__ __forceinline__ ull f2_pack(float lo, float hi) {
    ull p;
    asm("mov.b64 %0, {%1, %2};" : "=l"(p) : "r"(__float_as_uint(lo)), "r"(__float_as_uint(hi)));
    return p;
}

__device__ __forceinline__ void cp_async16(uint32_t smem_dst, const void* gsrc) {
    asm volatile("cp.async.cg.shared.global [%0], [%1], 16;"
                 :: "r"(smem_dst), "l"(gsrc) : "memory");
}
__device__ __forceinline__ void cp_commit() {
    asm volatile("cp.async.commit_group;" ::: "memory");
}
#define CP_WAIT(n) asm volatile("cp.async.wait_group %0;" :: "n"(n) : "memory")

// ---------------------------------------------------------------------------
// Kernel 1: fused q/k/v projection. grid = 3 * 512 = 1536 blocks x 256 threads.
//   path = blockIdx.x % 3 (interleaved: v's ctx read L2-hits behind k's).
//   32 rows/block, 4 rows/warp (8 warps).
//   WARP-AUTONOMOUS staging: each warp cp.asyncs its OWN 4 rows into a
//   PRIVATE 8 KB smem region (4 buffers x 2 KB), waits on its own cp.async
//   groups, computes -- ZERO __syncthreads in the main loop (R15 paid one
//   block-wide barrier per chunk, re-convoying all 8 warps every ~600 cyc).
//   Warps drift freely; one warp's FFMA burst overlaps others' LDS/LSU.
//   W (shared, read-only) staged once behind the single initial barrier.
//   Regs ~120, smem 32 KB (W) + 64 KB (x) = 96 KB -> 2 blocks/SM.
// ---------------------------------------------------------------------------
#define PROJ_SMEM (32768 + 8 * 4 * 2048)   // W + 8 warps x 4 bufs x 2 KB
__global__ void __launch_bounds__(256, 2) proj_fused_kernel(
    const float* __restrict__ x, const float* __restrict__ ctx,
    const float* __restrict__ Wq, const float* __restrict__ bq,
    const float* __restrict__ Wk, const float* __restrict__ bk,
    const float* __restrict__ Wv, const float* __restrict__ bv,
    float* __restrict__ q, float* __restrict__ k, float* __restrict__ v)
{
    extern __shared__ float smem[];
    float* sw = smem;            // 8 x 1024 floats = 32 KB
    float* xs = smem + 8 * 1024; // 8 warps x 4 bufs x 512 floats = 64 KB

    const int tid = threadIdx.x;
    const int warp = tid >> 5;
    const int lane = tid & 31;

    const int path = blockIdx.x % 3;        // 0 = q, 1 = k, 2 = v (interleaved)
    const int blk  = blockIdx.x / 3;        // 0..511

    const float* X    = (path == 0) ? x  : ctx;
    const float* W    = (path == 0) ? Wq : (path == 1) ? Wk : Wv;
    const float* bias = (path == 0) ? bq : (path == 1) ? bk : bv;
    float*       Y    = (path == 0) ? q  : (path == 1) ? k  : v;

    // Stage W transposed: sw[h*1024 + d] = W[d*8 + h] (float4 global loads)
    for (int i = tid; i < DIM * 2; i += 256) {
        int d = i >> 1, hg = (i & 1) * 4;
        float4 w4 = *reinterpret_cast<const float4*>(W + d * H + hg);
        sw[(hg + 0) * 1024 + d] = w4.x;
        sw[(hg + 1) * 1024 + d] = w4.y;
        sw[(hg + 2) * 1024 + d] = w4.z;
        sw[(hg + 3) * 1024 + d] = w4.w;
    }
    float bias_lane = (lane < H) ? bias[lane] : 0.0f;

    const int row0 = blk * 32;
    const int rbase = warp * 4;   // this warp's 4 rows

    // Warp-private buffer base (4 x 512 floats)
    float* wbuf = xs + warp * (4 * 512);
    const uint32_t wbuf_u32 = (uint32_t)__cvta_generic_to_shared(wbuf);

    // Per-lane staging slots: idx = lane + i*32 in [0,128):
    //   row_local = idx>>5 (0..3), seg = idx&31 (16B units).
    const float* gsrc_b[4];
    uint32_t     dst_b[4];
#pragma unroll
    for (int i = 0; i < 4; ++i) {
        int idx = lane + i * 32;
        int rl  = idx >> 5;
        int seg = idx & 31;
        gsrc_b[i] = X + (size_t)(row0 + rbase + rl) * DIM + seg * 4;
        dst_b[i]  = wbuf_u32 + (uint32_t)(rl * 128 + seg * 4) * 4u;
    }

    auto stage = [&](int c) {
        const uint32_t boff = (uint32_t)(c & 3) * 2048u;   // 512 floats * 4 B
#pragma unroll
        for (int i = 0; i < 4; ++i)
            cp_async16(dst_b[i] + boff, gsrc_b[i] + c * 128);
    };

    stage(0); cp_commit();
    stage(1); cp_commit();
    stage(2); cp_commit();

    __syncthreads();   // the ONLY block barrier: W visible to all warps

    ull acc0[H], acc1[H], acc2[H], acc3[H];
#pragma unroll
    for (int h = 0; h < H; ++h) {
        acc0[h] = 0ull; acc1[h] = 0ull; acc2[h] = 0ull; acc3[h] = 0ull;
    }

    const int d = lane * 4;

#pragma unroll 1
    for (int u = 0; u < 8; ++u) {
        // stage(u+3) targets buf (u+3)&3, last read by THIS warp as chunk
        // u-1 (already consumed); per-warp program order makes it safe.
        if (u < 5) { stage(u + 3); cp_commit(); CP_WAIT(3); }
        else if (u == 5) { CP_WAIT(2); }
        else if (u == 6) { CP_WAIT(1); }
        else             { CP_WAIT(0); }

        const float* xb = wbuf + (u & 3) * 512;
        ulonglong2 xv0 = *reinterpret_cast<const ulonglong2*>(xb +   0 + d);
        ulonglong2 xv1 = *reinterpret_cast<const ulonglong2*>(xb + 128 + d);
        ulonglong2 xv2 = *reinterpret_cast<const ulonglong2*>(xb + 256 + d);
        ulonglong2 xv3 = *reinterpret_cast<const ulonglong2*>(xb + 384 + d);

#pragma unroll
        for (int h = 0; h < H; ++h) {
            ulonglong2 wv = *reinterpret_cast<const ulonglong2*>(&sw[h * 1024 + u * 128 + d]);
            acc0[h] = ffma2(xv0.x, wv.x, acc0[h]);
            acc0[h] = ffma2(xv0.y, wv.y, acc0[h]);
            acc1[h] = ffma2(xv1.x, wv.x, acc1[h]);
            acc1[h] = ffma2(xv1.y, wv.y, acc1[h]);
            acc2[h] = ffma2(xv2.x, wv.x, acc2[h]);
            acc2[h] = ffma2(xv2.y, wv.y, acc2[h]);
            acc3[h] = ffma2(xv3.x, wv.x, acc3[h]);
            acc3[h] = ffma2(xv3.y, wv.y, acc3[h]);
        }
    }

    // Reduce across lanes; lane h keeps head h's sum
#pragma unroll
    for (int r = 0; r < 4; ++r) {
        float keep = 0.0f;
#pragma unroll
        for (int h = 0; h < H; ++h) {
            ull a = (r == 0) ? acc0[h] : (r == 1) ? acc1[h] : (r == 2) ? acc2[h] : acc3[h];
            float s = f2_lo(a) + f2_hi(a);
            s += __shfl_xor_sync(0xffffffffu, s, 16);
            s += __shfl_xor_sync(0xffffffffu, s, 8);
            s += __shfl_xor_sync(0xffffffffu, s, 4);
            s += __shfl_xor_sync(0xffffffffu, s, 2);
            s += __shfl_xor_sync(0xffffffffu, s, 1);
            if (lane == h) keep = s;
        }
        if (lane < H) Y[(size_t)(row0 + rbase + r) * H + lane] = keep + bias_lane;
    }
}

// ---------------------------------------------------------------------------
// Kernel 2: attention partials with key-split.
//   grid = 8 batches x 16 qchunks x 8 ksplits = 1024 blocks x 128 threads.
//   One thread per query; each block covers 256 keys (tile in smem, 16 KB).
//   Softmax without max-subtraction -> split partials add exactly.
// ---------------------------------------------------------------------------
__global__ void __launch_bounds__(128) attn_part_kernel(
    const float* __restrict__ q, const float* __restrict__ k,
    const float* __restrict__ v, float* __restrict__ pn,
    float* __restrict__ pd)
{
    __shared__ float ks[KS_LEN * H];   // 8 KB
    __shared__ float vs[KS_LEN * H];   // 8 KB

    const int tid = threadIdx.x;
    const int bb = blockIdx.x >> 7;            // batch
    const int qc = (blockIdx.x >> 3) & 15;     // query chunk
    const int sp = blockIdx.x & 7;             // key split
    const int row = bb * SQ + qc * 128 + tid;
    const int kbase = bb * SK + sp * KS_LEN;

    // Cooperative tile load: 256 keys x 8 floats for k and v
    {
        const float4* kg = reinterpret_cast<const float4*>(k + (size_t)kbase * H);
        const float4* vg = reinterpret_cast<const float4*>(v + (size_t)kbase * H);
        float4* ks4 = reinterpret_cast<float4*>(ks);
        float4* vs4 = reinterpret_cast<float4*>(vs);
#pragma unroll
        for (int i = 0; i < (KS_LEN * H / 4) / 128; ++i) {
            ks4[tid + i * 128] = kg[tid + i * 128];
            vs4[tid + i * 128] = vg[tid + i * 128];
        }
    }

    // Query in registers as four f32x2 packs
    ulonglong2 qa = *reinterpret_cast<const ulonglong2*>(q + (size_t)row * H);
    ulonglong2 qb = *reinterpret_cast<const ulonglong2*>(q + (size_t)row * H + 4);
    const ull q01 = qa.x, q23 = qa.y, q45 = qb.x, q67 = qb.y;

    __syncthreads();

    ull acc0 = 0ull, acc1 = 0ull, acc2 = 0ull, acc3 = 0ull;
    float denom = 0.0f;

#pragma unroll 8
    for (int t = 0; t < KS_LEN; ++t) {
        ulonglong2 k0 = *reinterpret_cast<const ulonglong2*>(&ks[t * H]);
        ulonglong2 k1 = *reinterpret_cast<const ulonglong2*>(&ks[t * H + 4]);
        ull s2 = fmul2(q67, k1.y);
        s2 = ffma2(q45, k1.x, s2);
        s2 = ffma2(q23, k0.y, s2);
        s2 = ffma2(q01, k0.x, s2);
        float s = f2_lo(s2) + f2_hi(s2);
        float e = __expf(s);
        denom += e;
        ull e2 = f2_pack(e, e);
        ulonglong2 v0 = *reinterpret_cast<const ulonglong2*>(&vs[t * H]);
        ulonglong2 v1 = *reinterpret_cast<const ulonglong2*>(&vs[t * H + 4]);
        acc0 = ffma2(e2, v0.x, acc0);
        acc1 = ffma2(e2, v0.y, acc1);
        acc2 = ffma2(e2, v1.x, acc2);
        acc3 = ffma2(e2, v1.y, acc3);
    }

    float4 o0, o1;
    o0.x = f2_lo(acc0); o0.y = f2_hi(acc0);
    o0.z = f2_lo(acc1); o0.w = f2_hi(acc1);
    o1.x = f2_lo(acc2); o1.y = f2_hi(acc2);
    o1.z = f2_lo(acc3); o1.w = f2_hi(acc3);
    float* pnr = pn + ((size_t)sp * ROWS + row) * H;
    *reinterpret_cast<float4*>(pnr)     = o0;
    *reinterpret_cast<float4*>(pnr + 4) = o1;
    pd[(size_t)sp * ROWS + row] = denom;
}

// ---------------------------------------------------------------------------
// Kernel 3: combine split-K partials + output projection.
//   grid = 1024 blocks x 256 threads, 16 rows/block.
//   Fold parallelized: threads 0..127 each fetch one (row, split) partial
//   into smem; threads 0..15 then fold 8 splits from smem (LDS, not LDG).
//   All threads project with Wo slice in registers (8 x float4 per thread).
// ---------------------------------------------------------------------------
#define OUT_RPB 16
__global__ void __launch_bounds__(256) outproj_kernel(
    const float* __restrict__ pn, const float* __restrict__ pd,
    const float* __restrict__ Wo, const float* __restrict__ bo,
    float* __restrict__ out)
{
    __shared__ float ps[OUT_RPB][KSPLIT][12];  // 9 used, pad to 12
    __shared__ float a_sm[OUT_RPB][H];

    const int t = threadIdx.x;
    const int j = t * 4;
    const int row0 = blockIdx.x * OUT_RPB;

    if (t < OUT_RPB * KSPLIT) {
        const int r = t >> 3;
        const int s = t & 7;
        const int row = row0 + r;
        const float* p = pn + ((size_t)s * ROWS + row) * H;
        float4 a = *reinterpret_cast<const float4*>(p);
        float4 b = *reinterpret_cast<const float4*>(p + 4);
        ps[r][s][0] = a.x; ps[r][s][1] = a.y; ps[r][s][2] = a.z; ps[r][s][3] = a.w;
        ps[r][s][4] = b.x; ps[r][s][5] = b.y; ps[r][s][6] = b.z; ps[r][s][7] = b.w;
        ps[r][s][8] = pd[(size_t)s * ROWS + row];
    }

    float4 w[H];
#pragma unroll
    for (int h = 0; h < H; ++h)
        w[h] = *reinterpret_cast<const float4*>(Wo + h * DIM + j);
    const float4 b4 = *reinterpret_cast<const float4*>(bo + j);

    __syncthreads();

    if (t < OUT_RPB) {
        float n[H] = {0.f, 0.f, 0.f, 0.f, 0.f, 0.f, 0.f, 0.f};
        float den = 0.0f;
#pragma unroll
        for (int s = 0; s < KSPLIT; ++s) {
#pragma unroll
            for (int h = 0; h < H; ++h) n[h] += ps[t][s][h];
            den += ps[t][s][8];
        }
        const float inv = 1.0f / den;
#pragma unroll
        for (int h = 0; h < H; ++h) a_sm[t][h] = n[h] * inv;
    }
    __syncthreads();

#pragma unroll
    for (int r = 0; r < OUT_RPB; ++r) {
        const int row = row0 + r;
        float4 o = b4;
#pragma unroll
        for (int h = 0; h < H; ++h) {
            float ah = a_sm[r][h];
            o.x = fmaf(ah, w[h].x, o.x);
            o.y = fmaf(ah, w[h].y, o.y);
            o.z = fmaf(ah, w[h].z, o.z);
            o.w = fmaf(ah, w[h].w, o.w);
        }
        *reinterpret_cast<float4*>(out + (size_t)row * DIM + j) = o;
    }
}

// ---------------------------------------------------------------------------
extern "C" void kernel_launch(void* const* d_in, const int* in_sizes, int n_in,
                              void* d_out, int out_size)
{
    const float* x       = (const float*)d_in[0];
    const float* context = (const float*)d_in[1];
    const float* Wq      = (const float*)d_in[2];
    const float* bq      = (const float*)d_in[3];
    const float* Wk      = (const float*)d_in[4];
    const float* bk      = (const float*)d_in[5];
    const float* Wv      = (const float*)d_in[6];
    const float* bv      = (const float*)d_in[7];
    const float* Wo      = (const float*)d_in[8];
    const float* bo      = (const float*)d_in[9];
    float* out = (float*)d_out;

    float* q_p;  cudaGetSymbolAddress((void**)&q_p,  g_q);
    float* k_p;  cudaGetSymbolAddress((void**)&k_p,  g_k);
    float* v_p;  cudaGetSymbolAddress((void**)&v_p,  g_v);
    float* pn_p; cudaGetSymbolAddress((void**)&pn_p, g_pn);
    float* pd_p; cudaGetSymbolAddress((void**)&pd_p, g_pd);

    cudaFuncSetAttribute(proj_fused_kernel,
                         cudaFuncAttributeMaxDynamicSharedMemorySize, PROJ_SMEM);

    proj_fused_kernel<<<3 * 512, 256, PROJ_SMEM>>>(x, context, Wq, bq, Wk, bk,
                                                   Wv, bv, q_p, k_p, v_p);
    attn_part_kernel<<<BATCH * 16 * KSPLIT, 128>>>(q_p, k_p, v_p, pn_p, pd_p);
    outproj_kernel<<<ROWS / OUT_RPB, 256>>>(pn_p, pd_p, Wo, bo, out);
}